// round 15
// baseline (speedup 1.0000x reference)
#include <cuda_runtime.h>
#include <cuda_bf16.h>
#include <cstdint>
#include <cstdlib>

// Problem constants (fixed shapes)
#define SOM_M   128
#define SOM_N   128
#define COMPS   16384     // SOM_M * SOM_N
#define BS      4096
#define DIM     768
#define NITER_F 1000.0f
#define ALPHA_F 0.3f
#define SIGMA_F 64.0f     // max(M,N)/2

typedef unsigned long long u64;

#if defined(__CUDA_ARCH_FEAT_SM103_ALL) || defined(__CUDA_ARCH_FEAT_SM100_ALL)
#define HAS_TC 1
#else
#define HAS_TC 0
#endif

// ---------------------------------------------------------------------------
// Device scratch (no allocations allowed in kernel_launch)
__device__ float g_wn[COMPS];
__device__ u64   g_key[BS];
__device__ int   g_bmu[BS];
__device__ int   g_hist[COMPS];
__device__ float g_T[COMPS];
__device__ float g_S[COMPS];

// Pre-swizzled bf16 hi/lo tile images.
// BMU (SW64, 8KB tiles of 128 rows x 32 k):
//   W : (ct2 0..127, kc 0..23, pol) at ((ct2*24+kc)*2+pol)*8192 bytes
//   X : (bt2 0..31,  kc 0..23, pol)
// Update (SW128, 16KB tiles of 128 d rows x 64 b):
//   XT: (dt 0..5, ukc 0..63, pol) at ((dt*64+ukc)*2+pol)*16384 bytes
__device__ uint4 g_wsw [128 * 24 * 2 * 512];    // 50.3 MB
__device__ uint4 g_xsw [ 32 * 24 * 2 * 512];    // 12.6 MB
__device__ uint4 g_xtsw[  6 * 64 * 2 * 1024];   // 12.6 MB

// ---------------------------------------------------------------------------
// PTX helpers (arch-neutral)
__device__ __forceinline__ uint32_t smem_u32(const void* p) {
    uint32_t a;
    asm("{ .reg .u64 t; cvta.to.shared.u64 t, %1; cvt.u32.u64 %0, t; }"
        : "=r"(a) : "l"(p));
    return a;
}
__device__ __forceinline__ u64 fma2(u64 a, u64 b, u64 c) {
    u64 d;
    asm("fma.rn.f32x2 %0, %1, %2, %3;" : "=l"(d) : "l"(a), "l"(b), "l"(c));
    return d;
}
__device__ __forceinline__ float lo2(u64 v) { return __uint_as_float((unsigned)v); }
__device__ __forceinline__ float hi2(u64 v) { return __uint_as_float((unsigned)(v >> 32)); }

__device__ __forceinline__ unsigned ordf(float f) {
    unsigned u = __float_as_uint(f);
    return (u & 0x80000000u) ? ~u : (u | 0x80000000u);
}

__device__ __forceinline__ uint32_t pack_bf16(float a, float b) {
    return ((uint32_t)__bfloat16_as_ushort(__float2bfloat16(b)) << 16) |
           __bfloat16_as_ushort(__float2bfloat16(a));
}
__device__ __forceinline__ void split8(const float* v, uint4& hi, uint4& lo) {
    uint32_t h[4], l[4];
    #pragma unroll
    for (int k = 0; k < 4; k++) {
        float a = v[2 * k], b = v[2 * k + 1];
        __nv_bfloat16 ha = __float2bfloat16(a), hb = __float2bfloat16(b);
        float la = a - __bfloat162float(ha);
        float lb = b - __bfloat162float(hb);
        h[k] = ((uint32_t)__bfloat16_as_ushort(hb) << 16) | __bfloat16_as_ushort(ha);
        l[k] = pack_bf16(la, lb);
    }
    hi = make_uint4(h[0], h[1], h[2], h[3]);
    lo = make_uint4(l[0], l[1], l[2], l[3]);
}

#define MBAR_INIT(a, c) asm volatile("mbarrier.init.shared.b64 [%0], %1;" :: "r"(a), "r"(c) : "memory")
#define MBAR_EXPECT_TX(a, bytes) \
    asm volatile("mbarrier.arrive.expect_tx.shared.b64 _, [%0], %1;" :: "r"(a), "r"(bytes) : "memory")
#define FENCE_ASYNC() asm volatile("fence.proxy.async.shared::cta;" ::: "memory")

__device__ __forceinline__ void mbar_wait(uint32_t mb, uint32_t parity) {
    asm volatile(
        "{\n\t"
        ".reg .pred P1;\n\t"
        "WL_%=:\n\t"
        "mbarrier.try_wait.parity.acquire.cta.shared::cta.b64 P1, [%0], %1, 0x989680;\n\t"
        "@P1 bra.uni WD_%=;\n\t"
        "bra.uni WL_%=;\n\t"
        "WD_%=:\n\t"
        "}"
        :: "r"(mb), "r"(parity) : "memory");
}

#if HAS_TC
// SW128 (update kernel) and SW64 (BMU) descriptors
static constexpr u64 DESC_BASE_SW128 =
    (u64(2) << 61) | (u64(1) << 46) | (u64(64) << 32) | (u64(1) << 16);
static constexpr u64 DESC_BASE_SW64 =
    (u64(4) << 61) | (u64(1) << 46) | (u64(32) << 32) | (u64(1) << 16);
__device__ __forceinline__ u64 make_desc(uint32_t addr) {
    return DESC_BASE_SW128 | ((u64)(addr >> 4) & 0x3FFF);
}
__device__ __forceinline__ u64 make_desc64(uint32_t addr) {
    return DESC_BASE_SW64 | ((u64)(addr >> 4) & 0x3FFF);
}

__device__ __forceinline__ void mma_f16_ss(uint32_t d_tmem, u64 a_desc, u64 b_desc,
                                           uint32_t idesc, bool en_d) {
    uint32_t en = en_d ? 1u : 0u;
    asm volatile(
        "{\n\t"
        ".reg .pred p;\n\t"
        "setp.ne.u32 p, %5, 0;\n\t"
        "tcgen05.mma.cta_group::1.kind::f16 [%0], %1, %2, %3, {%4,%4,%4,%4}, p;\n\t"
        "}"
        :: "r"(d_tmem), "l"(a_desc), "l"(b_desc), "r"(idesc), "r"(0u), "r"(en)
        : "memory");
}

__device__ __forceinline__ void bulk_cp(uint32_t dst, const void* src,
                                        uint32_t bytes, uint32_t mbar) {
    asm volatile(
        "cp.async.bulk.shared::cta.global.mbarrier::complete_tx::bytes "
        "[%0], [%1], %2, [%3];"
        :: "r"(dst), "l"(src), "r"(bytes), "r"(mbar) : "memory");
}

#define TC_ALLOC(sa, n)   asm volatile("tcgen05.alloc.cta_group::1.sync.aligned.shared::cta.b32 [%0], %1;" :: "r"(sa), "r"(n) : "memory")
#define TC_DEALLOC(tm, n) asm volatile("tcgen05.dealloc.cta_group::1.sync.aligned.b32 %0, %1;" :: "r"(tm), "r"(n))
#define TC_RELINQ()       asm volatile("tcgen05.relinquish_alloc_permit.cta_group::1.sync.aligned;")
#define TC_COMMIT(mb)     asm volatile("tcgen05.commit.cta_group::1.mbarrier::arrive::one.shared::cluster.b64 [%0];" :: "r"(mb) : "memory")
#define TC_FENCE_AFTER()  asm volatile("tcgen05.fence::after_thread_sync;" ::: "memory")
#define TC_WAIT_LD()      asm volatile("tcgen05.wait::ld.sync.aligned;" ::: "memory")

#define LDTM_X32(r, ta) \
    asm volatile( \
        "tcgen05.ld.sync.aligned.32x32b.x32.b32 " \
        "{%0,%1,%2,%3,%4,%5,%6,%7,%8,%9,%10,%11,%12,%13,%14,%15," \
        "%16,%17,%18,%19,%20,%21,%22,%23,%24,%25,%26,%27,%28,%29,%30,%31}, [%32];" \
        : "=r"((r)[0]),"=r"((r)[1]),"=r"((r)[2]),"=r"((r)[3]), \
          "=r"((r)[4]),"=r"((r)[5]),"=r"((r)[6]),"=r"((r)[7]), \
          "=r"((r)[8]),"=r"((r)[9]),"=r"((r)[10]),"=r"((r)[11]), \
          "=r"((r)[12]),"=r"((r)[13]),"=r"((r)[14]),"=r"((r)[15]), \
          "=r"((r)[16]),"=r"((r)[17]),"=r"((r)[18]),"=r"((r)[19]), \
          "=r"((r)[20]),"=r"((r)[21]),"=r"((r)[22]),"=r"((r)[23]), \
          "=r"((r)[24]),"=r"((r)[25]),"=r"((r)[26]),"=r"((r)[27]), \
          "=r"((r)[28]),"=r"((r)[29]),"=r"((r)[30]),"=r"((r)[31]) \
        : "r"(ta))
#endif  // HAS_TC

// ---------------------------------------------------------------------------
__global__ void prep_kernel() {
    int t = blockIdx.x * blockDim.x + threadIdx.x;
    if (t < COMPS) g_hist[t] = 0;
    if (t < BS)    g_key[t]  = 0ull;
}

__global__ void wn_kernel(const float* __restrict__ W) {
    int warp = threadIdx.x >> 5;
    int lane = threadIdx.x & 31;
    int c = blockIdx.x * 8 + warp;
    if (c >= COMPS) return;
    const float* row = &W[(size_t)c * DIM];
    float s = 0.f;
    #pragma unroll 6
    for (int i = lane; i < DIM; i += 32) {
        float v = row[i];
        s = fmaf(v, v, s);
    }
    #pragma unroll
    for (int o = 16; o > 0; o >>= 1) s += __shfl_xor_sync(0xFFFFFFFFu, s, o);
    if (lane == 0) g_wn[c] = s;
}

// W fp32 -> pre-swizzled SW64 bf16 hi/lo tile images (128 rows x 32 k, 8KB)
__global__ void split_w_kernel(const float* __restrict__ W) {
    int idx = blockIdx.x * blockDim.x + threadIdx.x;   // one uint4 (8 elems)
    if (idx >= COMPS * DIM / 8) return;
    int c  = idx / 96;
    int g  = idx % 96;
    int k0 = g * 8;
    int kc = k0 >> 5, kk = k0 & 31;
    float v[8];
    const float4* p = (const float4*)(W + (size_t)c * DIM + k0);
    float4 a = p[0], b = p[1];
    v[0]=a.x; v[1]=a.y; v[2]=a.z; v[3]=a.w;
    v[4]=b.x; v[5]=b.y; v[6]=b.z; v[7]=b.w;
    uint4 hi, lo;
    split8(v, hi, lo);
    int ct2 = c >> 7, r = c & 127;
    int off = r * 64 + kk * 2;
    int sw  = off ^ ((off >> 3) & 0x30);     // SW64 swizzle
    size_t base = (size_t)((ct2 * 24 + kc) * 2) * 8192;
    *(uint4*)((char*)g_wsw + base + sw)        = hi;
    *(uint4*)((char*)g_wsw + base + 8192 + sw) = lo;
}

// X -> SW64 b-major image (BMU A) AND SW128 d-major image (update B)
__global__ void split_x_t_kernel(const float* __restrict__ X) {
    __shared__ float tile[32][33];
    const int t  = threadIdx.x;
    const int tx = t & 31, ty = t >> 5;
    const int b0 = blockIdx.x * 32;
    const int d0 = blockIdx.y * 32;

    #pragma unroll
    for (int i = 0; i < 4; i++)
        tile[ty + 8 * i][tx] = X[(size_t)(b0 + ty + 8 * i) * DIM + d0 + tx];
    __syncthreads();

    if (t < 128) {
        // b-major SW64 (BMU A image)
        int brow = t >> 2, blk = t & 3;
        float v[8];
        #pragma unroll
        for (int k = 0; k < 8; k++) v[k] = tile[brow][blk * 8 + k];
        uint4 hi, lo;
        split8(v, hi, lo);
        int b = b0 + brow, d = d0 + blk * 8;
        int bt2 = b >> 7, r = b & 127;
        int kc = d >> 5, kk = d & 31;
        int off = r * 64 + kk * 2;
        int sw  = off ^ ((off >> 3) & 0x30);
        size_t base = (size_t)((bt2 * 24 + kc) * 2) * 8192;
        *(uint4*)((char*)g_xsw + base + sw)        = hi;
        *(uint4*)((char*)g_xsw + base + 8192 + sw) = lo;
    } else {
        // d-major SW128 (update B image) — unchanged layout
        int t2 = t - 128;
        int drow = t2 >> 2, blkb = t2 & 3;
        float v[8];
        #pragma unroll
        for (int k = 0; k < 8; k++) v[k] = tile[blkb * 8 + k][drow];
        uint4 hi, lo;
        split8(v, hi, lo);
        int b = b0 + blkb * 8, d = d0 + drow;
        int ukc = b >> 6, bblk = (b >> 3) & 7;
        int dt = d >> 7, r = d & 127;
        int off = r * 128 + bblk * 16;
        int sw  = off ^ ((off >> 3) & 0x70);
        size_t base = (size_t)((dt * 64 + ukc) * 2) * 16384;
        *(uint4*)((char*)g_xtsw + base + sw)         = hi;
        *(uint4*)((char*)g_xtsw + base + 16384 + sw) = lo;
    }
}

// ---------------------------------------------------------------------------
// K1: BMU. CTA tile 256 b x 256 c; KCH=32 SW64 tiles; double-buffered pipeline;
// 1 CTA/SM; TMEM 512 cols (4 D tiles of 128x128).
#define KCH      32
#define NCH      24
#define BMU_IDESC ((1u<<4) | (1u<<7) | (1u<<10) | ((128u/8)<<17) | ((128u/16)<<24))

#define SM_TMEMPTR 0
#define SM_MBAR    8                  // mma-done
#define SM_CPBAR0  16                 // copy-done buffer 0
#define SM_CPBAR1  24                 // copy-done buffer 1
#define SM_F       256
#define SM_BUF     1024               // 2 buffers x 64KB
#define SMEM_BMU   (SM_BUF + 2 * 65536)      // 132096

__global__ __launch_bounds__(256, 1) void bmu_mma_kernel(const float* __restrict__ X,
                                                         const float* __restrict__ W) {
    extern __shared__ char smem[];
    const int t  = threadIdx.x;
    const int c0 = blockIdx.x * 256;
    const int b0 = blockIdx.y * 256;

#if HAS_TC
    const uint32_t sb = smem_u32(smem);
    const int wid  = t >> 5;
    const int lane = t & 31;
    const int bt0  = blockIdx.y * 2;      // 128-row A sub-tiles
    const int ct0  = blockIdx.x * 2;      // 128-row B sub-tiles

    if (wid == 0) {
        TC_ALLOC(sb + SM_TMEMPTR, 512);
        TC_RELINQ();
    }
    if (t == 0) {
        MBAR_INIT(sb + SM_MBAR, 1);
        MBAR_INIT(sb + SM_CPBAR0, 1);
        MBAR_INIT(sb + SM_CPBAR1, 1);
    }
    __syncthreads();
    uint32_t tmem;
    asm volatile("ld.shared.b32 %0, [%1];" : "=r"(tmem) : "r"(sb + SM_TMEMPTR));

    // prologue: copies for chunk 0 into buffer 0
    if (t == 0) {
        MBAR_EXPECT_TX(sb + SM_CPBAR0, 8 * 8192);
        uint32_t dst = sb + SM_BUF;
        #pragma unroll
        for (int bg = 0; bg < 2; bg++)
            #pragma unroll
            for (int pol = 0; pol < 2; pol++)
                bulk_cp(dst + (bg * 2 + pol) * 8192,
                        (char*)g_xsw + (size_t)(((bt0 + bg) * 24 + 0) * 2 + pol) * 8192,
                        8192, sb + SM_CPBAR0);
        #pragma unroll
        for (int ct = 0; ct < 2; ct++)
            #pragma unroll
            for (int pol = 0; pol < 2; pol++)
                bulk_cp(dst + 32768 + (ct * 2 + pol) * 8192,
                        (char*)g_wsw + (size_t)(((ct0 + ct) * 24 + 0) * 2 + pol) * 8192,
                        8192, sb + SM_CPBAR0);
    }

    for (int kc = 0; kc < NCH; kc++) {
        const int s = kc & 1;
        // ALL threads: ordered waits so every thread observes each phase once.
        // Buffer s^1 (used by chunk kc-1... reused by kc+1) is free once MMA kc-1 done.
        if (kc >= 1) mbar_wait(sb + SM_MBAR, (uint32_t)((kc - 1) & 1));

        if (t == 0) {
            // issue copies for chunk kc+1 into buffer s^1 (overlaps MMA kc)
            if (kc + 1 < NCH) {
                uint32_t cpb = (s ^ 1) ? (sb + SM_CPBAR1) : (sb + SM_CPBAR0);
                MBAR_EXPECT_TX(cpb, 8 * 8192);
                uint32_t dst = sb + SM_BUF + (s ^ 1) * 65536;
                int kn = kc + 1;
                #pragma unroll
                for (int bg = 0; bg < 2; bg++)
                    #pragma unroll
                    for (int pol = 0; pol < 2; pol++)
                        bulk_cp(dst + (bg * 2 + pol) * 8192,
                                (char*)g_xsw + (size_t)(((bt0 + bg) * 24 + kn) * 2 + pol) * 8192,
                                8192, cpb);
                #pragma unroll
                for (int ct = 0; ct < 2; ct++)
                    #pragma unroll
                    for (int pol = 0; pol < 2; pol++)
                        bulk_cp(dst + 32768 + (ct * 2 + pol) * 8192,
                                (char*)g_wsw + (size_t)(((ct0 + ct) * 24 + kn) * 2 + pol) * 8192,
                                8192, cpb);
            }
            // wait for this chunk's data, then issue MMAs
            uint32_t cps = s ? (sb + SM_CPBAR1) : (sb + SM_CPBAR0);
            mbar_wait(cps, (uint32_t)((kc >> 1) & 1));

            uint32_t bufb = sb + SM_BUF + s * 65536;
            #pragma unroll
            for (int bg = 0; bg < 2; bg++) {
                u64 dah = make_desc64(bufb + (bg * 2 + 0) * 8192);
                u64 dal = make_desc64(bufb + (bg * 2 + 1) * 8192);
                #pragma unroll
                for (int ct = 0; ct < 2; ct++) {
                    u64 dbh = make_desc64(bufb + 32768 + (ct * 2 + 0) * 8192);
                    u64 dbl = make_desc64(bufb + 32768 + (ct * 2 + 1) * 8192);
                    uint32_t D = tmem + bg * 256 + ct * 128;
                    #pragma unroll
                    for (int s2 = 0; s2 < 2; s2++) {
                        mma_f16_ss(D, dah + 2 * s2, dbh + 2 * s2, BMU_IDESC,
                                   !(kc == 0 && s2 == 0));
                        mma_f16_ss(D, dal + 2 * s2, dbh + 2 * s2, BMU_IDESC, true);
                        mma_f16_ss(D, dah + 2 * s2, dbl + 2 * s2, BMU_IDESC, true);
                    }
                }
            }
            TC_COMMIT(sb + SM_MBAR);
        }
    }
    // final: all threads wait for chunk NCH-1 (in-order continuation)
    mbar_wait(sb + SM_MBAR, (uint32_t)((NCH - 1) & 1));
    TC_FENCE_AFTER();

    // epilogue: 8 warps; warp w -> b-group w>>2, subpartition w&3
    {
        const int bg  = wid >> 2;
        const int b   = b0 + bg * 128 + (wid & 3) * 32 + lane;
        u64 best = 0ull;
        #pragma unroll
        for (int ch = 0; ch < 8; ch++) {
            uint32_t r[32];
            LDTM_X32(r, tmem + bg * 256 + ch * 32);
            TC_WAIT_LD();
            int cbase = c0 + ch * 32;
            #pragma unroll
            for (int j = 0; j < 32; j++) {
                float score = __uint_as_float(r[j]) - 0.5f * g_wn[cbase + j];
                u64 key = ((u64)ordf(score) << 32) |
                          (0xFFFFFFFFu - (unsigned)(cbase + j));
                if (key > best) best = key;
            }
        }
        atomicMax(&g_key[b], best);
    }

    __syncthreads();
    if (wid == 0) TC_DEALLOC(tmem, 512);

#else  // ---------------- scalar f32x2 fallback (plain sm_103 cubin) --------
    #define FB_SST 34
    float* xs = (float*)smem;
    float* ws = (float*)(smem + 64 * FB_SST * 4);
    u64 (*red)[16] = (u64(*)[16])(smem + (64 + 128) * FB_SST * 4);

    const int tby = t >> 4;
    const int tcx = t & 15;

    for (int pass = 0; pass < 8; pass++) {
        const int bo = b0 + (pass >> 1) * 64;
        const int co = c0 + (pass & 1) * 128;

        u64 acc[4][8];
        #pragma unroll
        for (int i = 0; i < 4; i++)
            #pragma unroll
            for (int j = 0; j < 8; j++) acc[i][j] = 0ull;

        for (int k0 = 0; k0 < DIM; k0 += 32) {
            float2 xr[4], wr[8];
            #pragma unroll
            for (int r = 0; r < 4; r++) {
                int idx = t + 256 * r;
                int row = idx >> 4, cc = idx & 15;
                xr[r] = *(const float2*)&X[(size_t)(bo + row) * DIM + k0 + 2 * cc];
            }
            #pragma unroll
            for (int r = 0; r < 8; r++) {
                int idx = t + 256 * r;
                int row = idx >> 4, cc = idx & 15;
                wr[r] = *(const float2*)&W[(size_t)(co + row) * DIM + k0 + 2 * cc];
            }
            __syncthreads();
            #pragma unroll
            for (int r = 0; r < 4; r++) {
                int idx = t + 256 * r;
                int row = idx >> 4, cc = idx & 15;
                *(float2*)&xs[row * FB_SST + 2 * cc] = xr[r];
            }
            #pragma unroll
            for (int r = 0; r < 8; r++) {
                int idx = t + 256 * r;
                int row = idx >> 4, cc = idx & 15;
                *(float2*)&ws[row * FB_SST + 2 * cc] = wr[r];
            }
            __syncthreads();

            #pragma unroll
            for (int kp = 0; kp < 16; kp++) {
                u64 a2[4], b2[8];
                #pragma unroll
                for (int i = 0; i < 4; i++)
                    a2[i] = *(const u64*)&xs[(tby + 16 * i) * FB_SST + 2 * kp];
                #pragma unroll
                for (int j = 0; j < 8; j++)
                    b2[j] = *(const u64*)&ws[(tcx + 16 * j) * FB_SST + 2 * kp];
                #pragma unroll
                for (int i = 0; i < 4; i++)
                    #pragma unroll
                    for (int j = 0; j < 8; j++)
                        acc[i][j] = fma2(a2[i], b2[j], acc[i][j]);
            }
        }

        float wnj[8];
        #pragma unroll
        for (int j = 0; j < 8; j++) wnj[j] = g_wn[co + tcx + 16 * j];

        #pragma unroll
        for (int i = 0; i < 4; i++) {
            u64 best = 0ull;
            #pragma unroll
            for (int j = 0; j < 8; j++) {
                float score = lo2(acc[i][j]) + hi2(acc[i][j]) - 0.5f * wnj[j];
                unsigned cidx = (unsigned)(co + tcx + 16 * j);
                u64 key = ((u64)ordf(score) << 32) | (0xFFFFFFFFu - cidx);
                if (key > best) best = key;
            }
            red[tby + 16 * i][tcx] = best;
        }
        __syncthreads();
        if (t < 64) {
            u64 m = red[t][0];
            #pragma unroll
            for (int j = 1; j < 16; j++) {
                u64 v = red[t][j];
                if (v > m) m = v;
            }
            atomicMax(&g_key[bo + t], m);
        }
        __syncthreads();
    }
#endif
}

// decode packed keys -> bmu indices + histogram
__global__ void decode_hist_kernel() {
    int t = blockIdx.x * blockDim.x + threadIdx.x;
    if (t < BS) {
        int idx = (int)(0xFFFFFFFFu - (unsigned)(g_key[t] & 0xFFFFFFFFull));
        g_bmu[t] = idx;
        atomicAdd(&g_hist[idx], 1);
    }
}

// ---------------------------------------------------------------------------
// S[c] via separable convolution of the BMU histogram.
__global__ void conv1_kernel(const int* __restrict__ itp) {
    __shared__ float sf[128];
    const int t = threadIdx.x;
    const float decay = 1.0f - (float)(*itp) / NITER_F;
    const float sig = SIGMA_F * decay;
    const float inv_s2 = 1.0f / (sig * sig);
    if (t < 128) sf[t] = __expf(-(float)(t * t) * inv_s2);
    __syncthreads();
    int g = blockIdx.x * 256 + t;
    int i = g >> 7, cj = g & 127;
    const int* Hrow = &g_hist[i * 128];
    float s = 0.f;
    #pragma unroll 8
    for (int j = 0; j < 128; j++)
        s = fmaf((float)Hrow[j], sf[::abs(cj - j)], s);
    g_T[g] = s;
}

__global__ void conv2_kernel(const int* __restrict__ itp) {
    __shared__ float sf[128];
    const int t = threadIdx.x;
    const float decay = 1.0f - (float)(*itp) / NITER_F;
    const float alpha = ALPHA_F * decay;
    const float sig = SIGMA_F * decay;
    const float inv_s2 = 1.0f / (sig * sig);
    if (t < 128) sf[t] = __expf(-(float)(t * t) * inv_s2);
    __syncthreads();
    int g = blockIdx.x * 256 + t;
    int ci = g >> 7, cj = g & 127;
    float s = 0.f;
    #pragma unroll 8
    for (int i = 0; i < 128; i++)
        s = fmaf(sf[::abs(ci - i)], g_T[i * 128 + cj], s);
    g_S[g] = alpha * s;
}

// ---------------------------------------------------------------------------
// K2: update via tcgen05 (unchanged from R13). M=128 c x N=256 d per CTA, K=4096.
#define UKCH     64
#define UNCH     (BS / UKCH)
#define UA_HI    1024
#define UA_LO    (UA_HI + 16384)
#define UB       (UA_LO + 16384)
#define SMEM_UPD (UB + 2 * 32768)     // 99328

__global__ __launch_bounds__(256, 2) void upd_mma_kernel(
    const float* __restrict__ X, const float* __restrict__ W,
    const int* __restrict__ itp, float* __restrict__ out) {
    extern __shared__ char smem[];
    const int t  = threadIdx.x;
    const int c0 = blockIdx.x * 128;
    const int d0 = blockIdx.y * 256;

    const float decay = 1.0f - (float)(*itp) / NITER_F;
    const float alpha = ALPHA_F * decay;
    const float sig   = SIGMA_F * decay;
    const float inv_s2 = 1.0f / (sig * sig);

#if HAS_TC
    const uint32_t sb = smem_u32(smem);
    const int wid  = t >> 5;
    const int lane = t & 31;
    const int dt0  = blockIdx.y * 2;
    float* sf = (float*)(smem + SM_F);

    if (wid == 0) {
        TC_ALLOC(sb + SM_TMEMPTR, 256);
        TC_RELINQ();
    }
    if (t == 0) {
        MBAR_INIT(sb + SM_MBAR, 1);
        MBAR_INIT(sb + SM_CPBAR0, 1);
    }
    if (t < 128) sf[t] = __expf(-(float)(t * t) * inv_s2);
    __syncthreads();
    uint32_t tmem;
    asm volatile("ld.shared.b32 %0, [%1];" : "=r"(tmem) : "r"(sb + SM_TMEMPTR));

    for (int kc = 0; kc < UNCH; kc++) {
        const int b0 = kc * UKCH;
        if (kc > 0) mbar_wait(sb + SM_MBAR, (uint32_t)((kc - 1) & 1));

        if (t == 0) {
            MBAR_EXPECT_TX(sb + SM_CPBAR0, 4 * 16384);
            #pragma unroll
            for (int ct = 0; ct < 2; ct++) {
                const char* xb = (const char*)g_xtsw +
                                 (size_t)(((dt0 + ct) * 64 + kc) * 2) * 16384;
                bulk_cp(sb + UB + ct * 32768,         xb,         16384, sb + SM_CPBAR0);
                bulk_cp(sb + UB + ct * 32768 + 16384, xb + 16384, 16384, sb + SM_CPBAR0);
            }
        }

        // A (lr): 128 c rows x 32 b-pairs, generated on the fly (SW128)
        #pragma unroll
        for (int it = 0; it < 16; it++) {
            int e   = t + it * 256;
            int row = e >> 5, pb = e & 31;
            int c  = c0 + row;
            int ci = c >> 7, cj = c & 127;
            int m0 = g_bmu[b0 + 2 * pb];
            int m1 = g_bmu[b0 + 2 * pb + 1];
            float lr0 = alpha * sf[::abs(ci - (m0 >> 7))] * sf[::abs(cj - (m0 & 127))];
            float lr1 = alpha * sf[::abs(ci - (m1 >> 7))] * sf[::abs(cj - (m1 & 127))];
            __nv_bfloat16 h0 = __float2bfloat16(lr0);
            __nv_bfloat16 h1 = __float2bfloat16(lr1);
            float l0f = lr0 - __bfloat162float(h0);
            float l1f = lr1 - __bfloat162float(h1);
            uint32_t hp = ((uint32_t)__bfloat16_as_ushort(h1) << 16) |
                          __bfloat16_as_ushort(h0);
            uint32_t lp = pack_bf16(l0f, l1f);
            int off = row * 128 + pb * 4;
            int sw  = off ^ ((off >> 3) & 0x70);
            *(uint32_t*)(smem + UA_HI + sw) = hp;
            *(uint32_t*)(smem + UA_LO + sw) = lp;
        }
        FENCE_ASYNC();
        __syncthreads();

        if (t == 0) {
            mbar_wait(sb + SM_CPBAR0, (uint32_t)(kc & 1));
            u64 dah = make_desc(sb + UA_HI);
            u64 dal = make_desc(sb + UA_LO);
            #pragma unroll
            for (int ct = 0; ct < 2; ct++) {
                u64 dbh = make_desc(sb + UB + ct * 32768);
                u64 dbl = make_desc(sb + UB + ct * 32768 + 16384);
                uint32_t D = tmem + ct * 128;
                #pragma unroll
                for (int s = 0; s < 4; s++) {
                    mma_f16_ss(D, dah + 2 * s, dbh + 2 * s, BMU_IDESC,
                               !(kc == 0 && s == 0));
                    mma_f16_ss(D, dal + 2 * s, dbh + 2 * s, BMU_IDESC, true);
                    mma_f16_ss(D, dah + 2 * s, dbl + 2 * s, BMU_IDESC, true);
                }
            }
            TC_COMMIT(sb + SM_MBAR);
        }
    }
    mbar_wait(sb + SM_MBAR, (uint32_t)((UNCH - 1) & 1));
    TC_FENCE_AFTER();

    if (wid < 4) {
        const int c = c0 + wid * 32 + lane;
        const float om = 1.0f - g_S[c];
        #pragma unroll
        for (int ct = 0; ct < 2; ct++) {
            #pragma unroll
            for (int ch = 0; ch < 4; ch++) {
                uint32_t r[32];
                LDTM_X32(r, tmem + ct * 128 + ch * 32);
                TC_WAIT_LD();
                int dbase = d0 + ct * 128 + ch * 32;
                #pragma unroll
                for (int j = 0; j < 32; j++) {
                    size_t o = (size_t)c * DIM + dbase + j;
                    out[o] = fmaf(W[o], om, __uint_as_float(r[j]));
                }
            }
        }
    }

    __syncthreads();
    if (wid == 0) TC_DEALLOC(tmem, 256);

#else  // ---------------- scalar fallback (plain sm_103 cubin) --------------
    float* sf  = (float*)smem;
    float* xsf = (float*)(smem + 512);
    float* lrf = xsf + 8 * 256;

    if (t < 128) sf[t] = __expf(-(float)(t * t) * inv_s2);
    __syncthreads();

    const int cl = t & 127;
    const int dh = t >> 7;
    const int c  = c0 + cl;
    const int ci = c >> 7, cj = c & 127;

    float acc[128];
    #pragma unroll
    for (int d = 0; d < 128; d++) acc[d] = 0.f;

    for (int b0 = 0; b0 < BS; b0 += 8) {
        #pragma unroll
        for (int j = 0; j < 8; j++)
            xsf[j * 256 + t] = X[(size_t)(b0 + j) * DIM + d0 + t];
        if (t < 128) {
            #pragma unroll
            for (int j = 0; j < 8; j++) {
                int m = g_bmu[b0 + j];
                lrf[j * 128 + t] =
                    alpha * sf[::abs(ci - (m >> 7))] * sf[::abs(cj - (m & 127))];
            }
        }
        __syncthreads();
        #pragma unroll
        for (int j = 0; j < 8; j++) {
            float l = lrf[j * 128 + cl];
            #pragma unroll
            for (int d = 0; d < 128; d++)
                acc[d] = fmaf(l, xsf[j * 256 + dh * 128 + d], acc[d]);
        }
        __syncthreads();
    }

    const float om = 1.0f - g_S[c];
    #pragma unroll
    for (int d = 0; d < 128; d++) {
        size_t o = (size_t)c * DIM + d0 + dh * 128 + d;
        out[o] = fmaf(W[o], om, acc[d]);
    }
#endif
}

// ---------------------------------------------------------------------------
extern "C" void kernel_launch(void* const* d_in, const int* in_sizes, int n_in,
                              void* d_out, int out_size) {
    const float* X  = (const float*)d_in[0];   // embedded [4096, 768]
    const float* W  = (const float*)d_in[1];   // weights  [16384, 768]
    const int*   it = (const int*)d_in[2];     // scalar it
    float* out = (float*)d_out;                // [16384, 768]

    cudaFuncSetAttribute(bmu_mma_kernel,
                         cudaFuncAttributeMaxDynamicSharedMemorySize, SMEM_BMU);
    cudaFuncSetAttribute(upd_mma_kernel,
                         cudaFuncAttributeMaxDynamicSharedMemorySize, SMEM_UPD);

    prep_kernel<<<COMPS / 256, 256>>>();
    wn_kernel<<<COMPS / 8, 256>>>(W);
    split_w_kernel<<<COMPS * DIM / 8 / 256, 256>>>(W);
    dim3 grid_sx(BS / 32, DIM / 32);
    split_x_t_kernel<<<grid_sx, 256>>>(X);

    dim3 grid_bmu(COMPS / 256, BS / 256);
    bmu_mma_kernel<<<grid_bmu, 256, SMEM_BMU>>>(X, W);
    decode_hist_kernel<<<BS / 256, 256>>>();

    conv1_kernel<<<COMPS / 256, 256>>>(it);
    conv2_kernel<<<COMPS / 256, 256>>>(it);

    dim3 grid_upd(COMPS / 128, DIM / 256);
    upd_mma_kernel<<<grid_upd, 256, SMEM_UPD>>>(X, W, it, out);
}